// round 17
// baseline (speedup 1.0000x reference)
#include <cuda_runtime.h>
#include <math.h>

#define NB 8
#define NH 256
#define NW 256
#define NPIX (NB*NH*NW)
#define NCH 8              // 8 chunks of 32 rows
#define NBLK 512           // resident blocks, all wave-1 (co-residency 592 at occ 4)
#define NROW 2048          // phase-B items: one image row each
#define NHT 1024           // phase-C items: half-tiles of 512 px
#define THR 256

// Scratch (static __device__ per allocation rules; zero-initialized)
__device__ unsigned g_bits[NB*NCH*NW];   // bit i of [b][c][j] = (mask(c*32+i, j) != 0)
__device__ float    g_absd[NPIX];        // |dist| = fgd + bgd
__device__ float2   g_rowmax[NB*NH];     // per-row (fg_max, bg_max)
__device__ float    g_part[NHT*12];      // per-half-tile partials
__device__ unsigned g_bar1, g_bar2;      // global barrier counters
__device__ unsigned g_tick;              // final-combine ticket

// Vertical distance to nearest set bit (after XOR with inv) in column jo at row h.
__device__ __forceinline__ float vdist(const unsigned* sw, int jo, int h,
                                       int c0, int b0, unsigned inv) {
    unsigned m = (sw[c0 * NW + jo] ^ inv) & (0xFFFFFFFFu >> (31 - b0));
    int c = c0;
    while (m == 0u && c > 0) m = sw[--c * NW + jo] ^ inv;
    int du = m ? h - (c * 32 + 31 - __clz(m)) : 100000;
    m = (sw[c0 * NW + jo] ^ inv) & (0xFFFFFFFFu << b0);
    c = c0;
    while (m == 0u && c < NCH - 1) m = sw[++c * NW + jo] ^ inv;
    int dd = m ? (c * 32 + __ffs(m) - 1) - h : 100000;
    int d = min(du, dd);
    return (d >= 100000) ? 1e6f : (float)d;
}

__device__ __forceinline__ void grid_barrier(unsigned* cnt, int tid) {
    __syncthreads();
    __threadfence();
    if (tid == 0) {
        atomicAdd(cnt, 1u);
        volatile unsigned* vc = (volatile unsigned*)cnt;
        while (*vc < NBLK) __nanosleep(32);
    }
    __syncthreads();
}

// Fair-share schedule: rows (phase B). 2048 rows; SM residues r<124 get 14, else 13.
__device__ __forceinline__ void sched_rows(int blk, int& start, int& cnt) {
    int r = blk % 148, wave = blk / 148;
    if (r < 68) {            // 4 co-hosted blocks: {4,4,3,3}
        start = 14 * r + (wave == 0 ? 0 : (wave == 1 ? 4 : (wave == 2 ? 8 : 11)));
        cnt   = (wave <= 1) ? 4 : 3;
    } else if (r < 124) {    // 3 blocks: {5,5,4}
        start = 14 * r + (wave == 0 ? 0 : (wave == 1 ? 5 : 10));
        cnt   = (wave <= 1) ? 5 : 4;
    } else {                 // 3 blocks: {5,4,4}
        start = 14 * 124 + 13 * (r - 124) + (wave == 0 ? 0 : (wave == 1 ? 5 : 9));
        cnt   = (wave == 0) ? 5 : 4;
    }
}

// Fair-share schedule: half-tiles (phase C). 1024 items; residues r<136 get 7, else 6.
__device__ __forceinline__ void sched_ht(int blk, int& start, int& cnt) {
    int r = blk % 148, wave = blk / 148;
    if (r < 68) {            // 4 blocks: {2,2,2,1}
        start = 7 * r + 2 * wave;
        cnt   = (wave == 3) ? 1 : 2;
    } else if (r < 136) {    // 3 blocks: {3,2,2}
        start = 7 * r + (wave == 0 ? 0 : (wave == 1 ? 3 : 5));
        cnt   = (wave == 0) ? 3 : 2;
    } else {                 // 3 blocks: {2,2,2}
        start = 952 + 6 * (r - 136) + 2 * wave;
        cnt   = 2;
    }
}

__global__ __launch_bounds__(THR, 4)
void k_fused(const float* __restrict__ p0, const float* __restrict__ p1,
             const float* __restrict__ p2, const float* __restrict__ p3,
             const int* __restrict__ tg, float* __restrict__ out) {
    int blk = blockIdx.x;
    int tid = threadIdx.x;
    int lane = tid & 31, wq = tid >> 5;

    __shared__ unsigned sw[NCH * NW];     // 8 KB batch bitset
    __shared__ unsigned s_rowbits[32];
    __shared__ float sf[NW], sb[NW];
    __shared__ float smf[8], smb[8];
    __shared__ float sA[8], sB[8];
    __shared__ float sred[8][12];

    // ===== Phase A: every block packs ONE 32x32 tile =====
    {
        int b = blk >> 6, rem = blk & 63, c = rem >> 3, jg = rem & 7;
        int r0 = wq * 4;
        #pragma unroll
        for (int i = 0; i < 4; ++i) {
            int r = r0 + i;
            int val = tg[(b * NH + c * 32 + r) * NW + jg * 32 + lane];
            unsigned bal = __ballot_sync(0xffffffffu, val != 0);
            if (lane == 0) s_rowbits[r] = bal;
        }
        __syncthreads();
        if (tid < 32) {
            unsigned word = 0u;
            #pragma unroll
            for (int r = 0; r < 32; ++r)
                word |= ((s_rowbits[r] >> tid) & 1u) << r;
            g_bits[(b * NCH + c) * NW + jg * 32 + tid] = word;
        }
    }

    grid_barrier(&g_bar1, tid);

    // ===== Phase B: EDT rows via fair-share schedule =====
    {
        int start, cnt;
        sched_rows(blk, start, cnt);
        int cur_b = -1;
        for (int it = 0; it < cnt; ++it) {
            int row = start + it;
            int b = row >> 8, h = row & 255;
            if (b != cur_b) {
                __syncthreads();
                #pragma unroll
                for (int c = 0; c < NCH; ++c)
                    sw[c * NW + tid] = g_bits[(b * NCH + c) * NW + tid];
                __syncthreads();
                cur_b = b;
            }
            int c0 = h >> 5, b0 = h & 31;
            float gf = vdist(sw, tid, h, c0, b0, 0xFFFFFFFFu);  // fg: mask==0
            float gb = vdist(sw, tid, h, c0, b0, 0u);           // bg: mask==1
            sf[tid] = gf;
            sb[tid] = gb;
            __syncthreads();

            float bf = gf * gf;
            float bb2 = gb * gb;
            for (int r = 1; r < NW; ++r) {
                float c = (float)(r * r);
                if (c >= bf && c >= bb2) break;
                int jl = tid - r, jr = tid + r;
                if (jl >= 0) {
                    float a = sf[jl], x = sb[jl];
                    bf = fminf(bf, a * a + c);
                    bb2 = fminf(bb2, x * x + c);
                }
                if (jr < NW) {
                    float a = sf[jr], x = sb[jr];
                    bf = fminf(bf, a * a + c);
                    bb2 = fminf(bb2, x * x + c);
                }
            }
            float fgd = sqrtf(bf);
            float bgd = sqrtf(bb2);
            g_absd[row * NW + tid] = fgd + bgd;

            float mf = fgd, mb = bgd;
            #pragma unroll
            for (int o = 16; o; o >>= 1) {
                mf = fmaxf(mf, __shfl_down_sync(0xffffffffu, mf, o));
                mb = fmaxf(mb, __shfl_down_sync(0xffffffffu, mb, o));
            }
            if (lane == 0) { smf[wq] = mf; smb[wq] = mb; }
            __syncthreads();
            if (tid == 0) {
                #pragma unroll
                for (int q = 1; q < 8; ++q) { mf = fmaxf(mf, smf[q]); mb = fmaxf(mb, smb[q]); }
                g_rowmax[row] = make_float2(mf, mb);
            }
            __syncthreads();
        }
    }

    grid_barrier(&g_bar2, tid);

    // ===== Phase C: loss half-tiles (512 px, 2 px/thread) via fair-share =====
    {
        int start, cnt;
        sched_ht(blk, start, cnt);
        int cur_b = -1;
        float inv3 = 0.f, cfl = 0.f;
        for (int it = 0; it < cnt; ++it) {
            int ht = start + it;
            int b = ht >> 7;
            if (b != cur_b) {
                __syncthreads();
                float2 rm = g_rowmax[b * NH + tid];
                float mf = rm.x, mb = rm.y;
                #pragma unroll
                for (int o = 16; o; o >>= 1) {
                    mf = fmaxf(mf, __shfl_down_sync(0xffffffffu, mf, o));
                    mb = fmaxf(mb, __shfl_down_sync(0xffffffffu, mb, o));
                }
                if (lane == 0) { sA[wq] = mf; sB[wq] = mb; }
                __syncthreads();
                mf = sA[0]; mb = sB[0];
                #pragma unroll
                for (int q = 1; q < 8; ++q) { mf = fmaxf(mf, sA[q]); mb = fmaxf(mb, sB[q]); }
                float md = fmaxf(mf, mb);
                bool valid = (mb < 9e5f) && (md > 0.f);
                inv3 = valid ? 3.0f / fmaxf(md, 1e-12f) : 0.f;
                cfl  = valid ? 1.f : 0.f;
                cur_b = b;
            }

            int pix = b * (NH * NW) + (ht & 127) * 512 + tid * 2;
            float2 x0 = *(const float2*)(p0 + pix);
            float2 x1 = *(const float2*)(p1 + pix);
            float2 x2 = *(const float2*)(p2 + pix);
            float2 x3 = *(const float2*)(p3 + pix);
            int2   tv = *(const int2*)(tg + pix);
            float2 ad = *(const float2*)(g_absd + pix);

            float X[2][4] = { {x0.x, x1.x, x2.x, x3.x},
                              {x0.y, x1.y, x2.y, x3.y} };
            float T[2]  = { (float)tv.x, (float)tv.y };
            float AD[2] = { ad.x, ad.y };

            float acc[12];
            #pragma unroll
            for (int k = 0; k < 12; ++k) acc[k] = 0.f;

            #pragma unroll
            for (int e = 0; e < 2; ++e) {
                float t = T[e];
                float w = 1.f + cfl * __expf(-AD[e] * inv3);
                float tw = t * w;
                float al = (t == 1.f) ? 0.25f : 0.75f;
                float s12 = 1.f - 2.f * t;
                #pragma unroll
                for (int k = 0; k < 4; ++k) {
                    float x = X[e][k];
                    float y = (t == 1.f) ? -x : x;
                    float a = __expf(-fabsf(y));
                    float ce = fmaxf(y, 0.f) + __logf(1.f + a);
                    float r = __fdividef(1.f, 1.f + a);
                    float q = ((y >= 0.f) ? 1.f : a) * r;     // sigmoid(y) = 1 - p_t
                    acc[k] += al * q * q * ce;                 // focal
                    float p = t + s12 * q;                     // sigmoid(x)
                    float pw = p * w;
                    acc[4 + k] += pw * t;                      // inter
                    acc[8 + k] += pw + tw;                     // (p + t) * w
                }
            }

            #pragma unroll
            for (int k = 0; k < 12; ++k) {
                #pragma unroll
                for (int o = 16; o; o >>= 1)
                    acc[k] += __shfl_down_sync(0xffffffffu, acc[k], o);
            }
            if (lane == 0) {
                #pragma unroll
                for (int k = 0; k < 12; ++k) sred[wq][k] = acc[k];
            }
            __syncthreads();
            if (tid < 12) {
                float s = 0.f;
                #pragma unroll
                for (int q = 0; q < 8; ++q) s += sred[q][tid];
                g_part[ht * 12 + tid] = s;
            }
            __syncthreads();
        }
    }

    // ===== Ticket: last block does the deterministic final combine =====
    __threadfence();
    __syncthreads();
    __shared__ unsigned ticket;
    if (tid == 0) ticket = atomicAdd(&g_tick, 1u);
    __syncthreads();
    if (ticket != NBLK - 1) return;
    __threadfence();

    __shared__ float s_iou[NB][4];
    __shared__ float sfin[4][THR];
    // IoU: warp wq handles batch wq (128 half-tiles each)
    {
        float in_[4] = {0.f,0.f,0.f,0.f}, u_[4] = {0.f,0.f,0.f,0.f};
        for (int r = lane; r < 128; r += 32) {
            const float* pp = g_part + (wq * 128 + r) * 12;
            #pragma unroll
            for (int k = 0; k < 4; ++k) { in_[k] += pp[4 + k]; u_[k] += pp[8 + k]; }
        }
        #pragma unroll
        for (int k = 0; k < 4; ++k) {
            #pragma unroll
            for (int o = 16; o; o >>= 1) {
                in_[k] += __shfl_down_sync(0xffffffffu, in_[k], o);
                u_[k]  += __shfl_down_sync(0xffffffffu, u_[k],  o);
            }
        }
        if (lane == 0) {
            #pragma unroll
            for (int k = 0; k < 4; ++k) {
                float inter = in_[k];
                float un = u_[k] - inter;
                s_iou[wq][k] = (inter + 1e-6f) / (un + 1e-6f);
            }
        }
    }

    // Focal: tree reduce over NHT half-tile partials
    float f[4] = {0.f,0.f,0.f,0.f};
    for (int i = tid; i < NHT; i += THR) {
        const float* pp = g_part + i * 12;
        #pragma unroll
        for (int k = 0; k < 4; ++k) f[k] += pp[k];
    }
    #pragma unroll
    for (int k = 0; k < 4; ++k) sfin[k][tid] = f[k];
    __syncthreads();
    for (int s = 128; s; s >>= 1) {
        if (tid < s) {
            #pragma unroll
            for (int k = 0; k < 4; ++k) sfin[k][tid] += sfin[k][tid + s];
        }
        __syncthreads();
    }

    if (tid == 0) {
        const float wgt[4] = { 1.0f, 0.4f, 0.2f, 0.4f / 3.0f };
        float total = 0.f;
        #pragma unroll
        for (int k = 0; k < 4; ++k) {
            float fm = sfin[k][0] / (float)NPIX;
            float is = 0.f;
            #pragma unroll
            for (int b2 = 0; b2 < NB; ++b2) is += s_iou[b2][k];
            float il = 1.f - is / (float)NB;
            total += wgt[k] * (fm + il);
        }
        out[0] = total;
        // reset counters for the next graph replay
        g_bar1 = 0u; g_bar2 = 0u; g_tick = 0u;
    }
}

extern "C" void kernel_launch(void* const* d_in, const int* in_sizes, int n_in,
                              void* d_out, int out_size) {
    const float* p0 = (const float*)d_in[0];   // pred_main
    const float* p1 = (const float*)d_in[1];   // aux0
    const float* p2 = (const float*)d_in[2];   // aux1
    const float* p3 = (const float*)d_in[3];   // aux2
    const int*   tg = (const int*)d_in[4];     // targets

    k_fused<<<NBLK, THR>>>(p0, p1, p2, p3, tg, (float*)d_out);
}